// round 13
// baseline (speedup 1.0000x reference)
#include <cuda_runtime.h>
#include <math.h>

#define NN 4096
#define CEXP 144.269504089f   /* (1/TAU) * log2(e) */
#define RWIN 0.3725f          /* sqrt(20 / CEXP): exp2 term < 2^-20 beyond */

static __device__ float g_xs[NN + 4];   // preds sorted ascending (+padding)
static __device__ float g_ts[NN + 4];   // target permuted alongside (+padding)
static __device__ float g_y[NN];        // y_sorted
static __device__ float g_ss[NN];       // s = 100*y sorted DESCENDING
static __device__ int   g_sidx[NN];     // original indices of that sort

// ---- PDL primitives --------------------------------------------------------
__device__ __forceinline__ void pdl_wait() {
    asm volatile("griddepcontrol.wait;" ::: "memory");
}
__device__ __forceinline__ void pdl_trigger() {
    asm volatile("griddepcontrol.launch_dependents;" ::: "memory");
}

// ---------------------------------------------------------------------------
// Kernel A: rank-by-count sort of (preds, target) by preds ascending.
// 512 blocks x 256 thr, ONE row per warp (max occupancy / latency hiding).
// ---------------------------------------------------------------------------
__global__ void __launch_bounds__(256)
rank_scatter_pairs(const float* __restrict__ preds,
                   const float* __restrict__ target) {
    const unsigned FULL = 0xffffffffu;
    __shared__ float sx[NN];
    float4* sx4 = (float4*)sx;
    const float4* p4 = (const float4*)preds;
    for (int i = threadIdx.x; i < NN / 4; i += 256) sx4[i] = p4[i];
    __syncthreads();

    int warp = threadIdx.x >> 5;
    int lane = threadIdx.x & 31;
    int row  = blockIdx.x * 8 + warp;
    float x0 = sx[row];
    int c0 = 0;
    #pragma unroll 8
    for (int t = 0; t < NN / 128; t++) {
        int j = t * 128 + lane * 4;
        float4 v = sx4[j >> 2];
        c0 += (v.x < x0) || (v.x == x0 && (j + 0) < row);
        c0 += (v.y < x0) || (v.y == x0 && (j + 1) < row);
        c0 += (v.z < x0) || (v.z == x0 && (j + 2) < row);
        c0 += (v.w < x0) || (v.w == x0 && (j + 3) < row);
    }
    #pragma unroll
    for (int off = 16; off; off >>= 1) c0 += __shfl_xor_sync(FULL, c0, off);
    if (lane == 0) {
        g_xs[c0] = x0; g_ts[c0] = target[row];
    }
    if (blockIdx.x == 0 && threadIdx.x < 4) {
        g_xs[NN + threadIdx.x] = 1e30f;
        g_ts[NN + threadIdx.x] = 0.0f;
    }
    pdl_trigger();
}

// ---------------------------------------------------------------------------
// Kernel B: y_sorted[i] = softmax_j(-(xs_i - x_j)^2/tau) . t_j
// ---------------------------------------------------------------------------
__global__ void __launch_bounds__(1024)
ysoft_kernel() {
    const unsigned FULL = 0xffffffffu;
    __shared__ float sx[NN + 4];
    __shared__ float st_[NN + 4];
    pdl_wait();
    {
        float4* a = (float4*)sx;
        float4* b = (float4*)st_;
        const float4* ga = (const float4*)g_xs;
        const float4* gb = (const float4*)g_ts;
        a[threadIdx.x] = ga[threadIdx.x];
        b[threadIdx.x] = gb[threadIdx.x];
        if (threadIdx.x == 0) {
            a[NN / 4] = ga[NN / 4];
            b[NN / 4] = gb[NN / 4];
        }
    }
    __syncthreads();

    const int lane = threadIdx.x & 31;
    const int warp = threadIdx.x >> 5;
    const int row = blockIdx.x * 32 + warp;
    const float xv = sx[row];

    int lim = 0;
    if (lane < 2) {
        float tgt = (lane == 0) ? (xv - RWIN) : (xv + RWIN);
        int l = 0, r = NN;
        while (l < r) {
            int m = (l + r) >> 1;
            bool go = (lane == 0) ? (sx[m] < tgt) : (sx[m] <= tgt);
            if (go) l = m + 1; else r = m;
        }
        lim = l;
    }
    int lo = __shfl_sync(FULL, lim, 0);
    int hi = __shfl_sync(FULL, lim, 1);

    float se = 0.f, su = 0.f;
    int j0 = (lo & ~3) + lane * 4;
    for (int j = j0; j < hi; j += 128) {
        float4 x4 = *reinterpret_cast<const float4*>(sx + j);
        float4 t4 = *reinterpret_cast<const float4*>(st_ + j);
        float d0 = xv - x4.x, d1 = xv - x4.y, d2 = xv - x4.z, d3 = xv - x4.w;
        float a0 = (d0 * d0) * (-CEXP);
        float a1 = (d1 * d1) * (-CEXP);
        float a2 = (d2 * d2) * (-CEXP);
        float a3 = (d3 * d3) * (-CEXP);
        float e0, e1, e2, e3;
        asm("ex2.approx.f32 %0, %1;" : "=f"(e0) : "f"(a0));
        asm("ex2.approx.f32 %0, %1;" : "=f"(e1) : "f"(a1));
        asm("ex2.approx.f32 %0, %1;" : "=f"(e2) : "f"(a2));
        asm("ex2.approx.f32 %0, %1;" : "=f"(e3) : "f"(a3));
        se += e0 + e1 + e2 + e3;
        su = fmaf(e0, t4.x, su);
        su = fmaf(e1, t4.y, su);
        su = fmaf(e2, t4.z, su);
        su = fmaf(e3, t4.w, su);
    }
    for (int off = 16; off; off >>= 1) {
        se += __shfl_down_sync(FULL, se, off);
        su += __shfl_down_sync(FULL, su, off);
    }
    if (lane == 0) g_y[row] = su / se;
    pdl_trigger();
}

// ---------------------------------------------------------------------------
// Kernel D: rank-by-count DESCENDING argsort of y, one row per warp.
// ---------------------------------------------------------------------------
__global__ void __launch_bounds__(256)
rank_scatter_y() {
    const unsigned FULL = 0xffffffffu;
    __shared__ float sy[NN];
    pdl_wait();
    float4* sy4 = (float4*)sy;
    const float4* y4 = (const float4*)g_y;
    for (int i = threadIdx.x; i < NN / 4; i += 256) sy4[i] = y4[i];
    __syncthreads();

    int warp = threadIdx.x >> 5;
    int lane = threadIdx.x & 31;
    int row  = blockIdx.x * 8 + warp;
    float y0 = sy[row];
    int c0 = 0;
    #pragma unroll 8
    for (int t = 0; t < NN / 128; t++) {
        int j = t * 128 + lane * 4;
        float4 v = sy4[j >> 2];
        c0 += (v.x > y0) || (v.x == y0 && (j + 0) < row);
        c0 += (v.y > y0) || (v.y == y0 && (j + 1) < row);
        c0 += (v.z > y0) || (v.z == y0 && (j + 2) < row);
        c0 += (v.w > y0) || (v.w == y0 && (j + 3) < row);
    }
    #pragma unroll
    for (int off = 16; off; off >>= 1) c0 += __shfl_xor_sync(FULL, c0, off);
    if (lane == 0) {
        g_ss[c0] = y0 * 100.0f; g_sidx[c0] = row;
    }
    pdl_trigger();
}

// ---------------------------------------------------------------------------
// Kernel C: soft_rank via PAV + loss. Single block, 1024 thr. (R10 version)
// ---------------------------------------------------------------------------
__global__ void __launch_bounds__(1024)
rank_kernel(float* out, int out_size) {
    extern __shared__ char smem_raw[];
    float4* pb     = (float4*)smem_raw;            // NN  (pre-blocks / stack)
    float*  r      = (float*)(pb + NN);            // NN  (zc prefix, then ranks)
    float*  fmean  = r + NN;                       // NN
    int*    bstart = (int*)(fmean + NN);           // NN+1
    int*    fstart = bstart + NN + 1;              // NN+1
    float*  sprev  = (float*)(fstart + NN + 1);    // 1024

    __shared__ int   warpTotI[32];
    __shared__ float warpTotF[32];
    __shared__ int   warpOffI[32];
    __shared__ float warpOffF[32];
    __shared__ int   s_m, s_nb;
    __shared__ float s_red[32];

    const unsigned FULL = 0xffffffffu;
    int tid  = threadIdx.x;
    int lane = tid & 31;
    int warp = tid >> 5;
    const int base = tid * 4;

    pdl_wait();
    float4 sv = ((const float4*)g_ss)[tid];
    int4   si = ((const int4*)g_sidx)[tid];
    sprev[tid] = sv.w;
    __syncthreads();

    float prev = (tid == 0) ? sv.x : sprev[tid - 1];
    int b0 = (base > 0) ? (prev - sv.x > 1.0f) : 0;
    int b1 = (sv.x - sv.y > 1.0f);
    int b2 = (sv.y - sv.z > 1.0f);
    int b3 = (sv.z - sv.w > 1.0f);
    int cb = b0 + b1 + b2 + b3;
    float zt = (sv.x + sv.y + sv.z + sv.w) - (float)(4 * NN - 4 * base - 6);

    int ic = cb; float fc = zt;
    for (int off = 1; off < 32; off <<= 1) {
        int   ui = __shfl_up_sync(FULL, ic, off);
        float uf = __shfl_up_sync(FULL, fc, off);
        if (lane >= off) { ic += ui; fc += uf; }
    }
    if (lane == 31) { warpTotI[warp] = ic; warpTotF[warp] = fc; }
    __syncthreads();
    if (warp == 0) {
        int   ti = warpTotI[lane];
        float tf = warpTotF[lane];
        int   vi = ti; float vf = tf;
        for (int off = 1; off < 32; off <<= 1) {
            int   ui = __shfl_up_sync(FULL, vi, off);
            float uf = __shfl_up_sync(FULL, vf, off);
            if (lane >= off) { vi += ui; vf += uf; }
        }
        warpOffI[lane] = vi - ti;
        warpOffF[lane] = vf - tf;
    }
    __syncthreads();
    int   exI = warpOffI[warp] + (ic - cb);
    float exF = warpOffF[warp] + (fc - zt);

    {
        int cc = exI;
        float zc = exF;
        cc += b0; if (b0) bstart[cc] = base + 0;
        zc += sv.x - (float)(NN - base - 0); r[base + 0] = zc;
        cc += b1; if (b1) bstart[cc] = base + 1;
        zc += sv.y - (float)(NN - base - 1); r[base + 1] = zc;
        cc += b2; if (b2) bstart[cc] = base + 2;
        zc += sv.z - (float)(NN - base - 2); r[base + 2] = zc;
        cc += b3; if (b3) bstart[cc] = base + 3;
        zc += sv.w - (float)(NN - base - 3); r[base + 3] = zc;
        if (tid == 0) bstart[0] = 0;
        if (tid == 1023) { s_m = cc + 1; bstart[cc + 1] = NN; }
    }
    __syncthreads();

    int m = s_m;
    for (int b = tid; b < m; b += 1024) {
        int st_ = bstart[b], en = bstart[b + 1];
        float lo_ = (st_ > 0) ? r[st_ - 1] : 0.f;
        pb[b] = make_float4(r[en - 1] - lo_, (float)(en - st_), (float)st_, 0.f);
    }
    __syncthreads();

    if (tid == 0) {
        int sp = 0;
        float4 c0 = pb[0];
        float tsum = c0.x, tcnt = c0.y, tstf = c0.z;
        float4 nxt = (m > 1) ? pb[1] : make_float4(0, 0, 0, 0);
        for (int b = 1; b < m; b++) {
            float4 c = nxt;
            if (b + 1 < m) nxt = pb[b + 1];
            float nsum = c.x, ncnt = c.y, nstf = c.z;
            bool havetop = true;
            while (havetop && tsum * ncnt <= nsum * tcnt) {
                nsum += tsum; ncnt += tcnt; nstf = tstf;
                if (sp > 0) {
                    sp--;
                    float4 tpv = pb[sp];
                    tsum = tpv.x; tcnt = tpv.y; tstf = tpv.z;
                } else {
                    havetop = false;
                }
            }
            if (havetop) {
                pb[sp] = make_float4(tsum, tcnt, tstf, 0.f);
                sp++;
            }
            tsum = nsum; tcnt = ncnt; tstf = nstf;
        }
        for (int q_ = 0; q_ < sp; q_++) {
            float4 v = pb[q_];
            fstart[q_] = (int)v.z;
            fmean[q_]  = v.x / v.y;
        }
        fstart[sp] = (int)tstf;
        fmean[sp]  = tsum / tcnt;
        fstart[sp + 1] = NN;
        s_nb = sp + 1;
    }
    __syncthreads();

    int nb = s_nb;
    #pragma unroll
    for (int e = 0; e < 4; e++) {
        int k = base + e;
        int l = 0, h = nb;
        while (l + 1 < h) {
            int mid = (l + h) >> 1;
            if (fstart[mid] <= k) l = mid; else h = mid;
        }
        float sval = (e == 0) ? sv.x : (e == 1) ? sv.y : (e == 2) ? sv.z : sv.w;
        int dst = (e == 0) ? si.x : (e == 1) ? si.y : (e == 2) ? si.z : si.w;
        r[dst] = sval - fmean[l];
    }
    __syncthreads();

    float acc = 0.f;
    for (int i = tid; i < NN - 1; i += 1024) acc += fabsf(r[i + 1] - r[i]);
    for (int off = 16; off; off >>= 1) acc += __shfl_down_sync(FULL, acc, off);
    if (lane == 0) s_red[warp] = acc;
    __syncthreads();
    if (warp == 0) {
        float a2 = s_red[lane];
        for (int off = 16; off; off >>= 1) a2 += __shfl_down_sync(FULL, a2, off);
        if (lane == 0) {
            float xi = 1.0f - 3.0f * a2 / ((float)NN * (float)NN - 1.0f);
            out[0] = -xi;
            if (out_size > 1) out[1] = xi;
        }
    }
}

// ---------------------------------------------------------------------------
extern "C" void kernel_launch(void* const* d_in, const int* in_sizes, int n_in,
                              void* d_out, int out_size) {
    const float* preds  = (const float*)d_in[0];
    const float* target = (const float*)d_in[1];
    float* out = (float*)d_out;

    size_t smemR = (size_t)NN * 32 + 8 + 4096;
    static int configured = 0;
    if (!configured) {
        cudaFuncSetAttribute(rank_kernel,
                             cudaFuncAttributeMaxDynamicSharedMemorySize,
                             (int)smemR);
        configured = 1;
    }

    rank_scatter_pairs<<<512, 256>>>(preds, target);

    cudaLaunchAttribute attr[1];
    attr[0].id = cudaLaunchAttributeProgrammaticStreamSerialization;
    attr[0].val.programmaticStreamSerializationAllowed = 1;

    {
        cudaLaunchConfig_t cfg = {};
        cfg.gridDim = dim3(NN / 32, 1, 1);
        cfg.blockDim = dim3(1024, 1, 1);
        cfg.dynamicSmemBytes = 0;
        cfg.attrs = attr;
        cfg.numAttrs = 1;
        cudaLaunchKernelEx(&cfg, ysoft_kernel);
    }
    {
        cudaLaunchConfig_t cfg = {};
        cfg.gridDim = dim3(512, 1, 1);
        cfg.blockDim = dim3(256, 1, 1);
        cfg.dynamicSmemBytes = 0;
        cfg.attrs = attr;
        cfg.numAttrs = 1;
        cudaLaunchKernelEx(&cfg, rank_scatter_y);
    }
    {
        cudaLaunchConfig_t cfg = {};
        cfg.gridDim = dim3(1, 1, 1);
        cfg.blockDim = dim3(1024, 1, 1);
        cfg.dynamicSmemBytes = smemR;
        cfg.attrs = attr;
        cfg.numAttrs = 1;
        cudaLaunchKernelEx(&cfg, rank_kernel, out, out_size);
    }
}

// round 14
// speedup vs baseline: 1.0906x; 1.0906x over previous
#include <cuda_runtime.h>
#include <math.h>

#define NN 4096
#define CEXP 144.269504089f   /* (1/TAU) * log2(e) */
#define RWIN 0.3725f          /* sqrt(20 / CEXP): exp2 term < 2^-20 beyond */

static __device__ float g_xs[NN + 4];   // preds sorted ascending (+padding)
static __device__ float g_ts[NN + 4];   // target permuted alongside (+padding)
static __device__ float g_y[NN];        // y_sorted
static __device__ float g_ss[NN];       // s = 100*y sorted DESCENDING
static __device__ int   g_sidx[NN];     // original indices of that sort

// ---- PDL primitives --------------------------------------------------------
__device__ __forceinline__ void pdl_wait() {
    asm volatile("griddepcontrol.wait;" ::: "memory");
}
__device__ __forceinline__ void pdl_trigger() {
    asm volatile("griddepcontrol.launch_dependents;" ::: "memory");
}

// ---------------------------------------------------------------------------
// Kernel A: rank-by-count sort of (preds, target) by preds ascending.
// 128 blocks x 256 thr (single wave, 1 CTA/SM), 4 rows per warp:
// each float4 smem load is compared against 4 register row-values.
// ---------------------------------------------------------------------------
__global__ void __launch_bounds__(256)
rank_scatter_pairs(const float* __restrict__ preds,
                   const float* __restrict__ target) {
    const unsigned FULL = 0xffffffffu;
    __shared__ float sx[NN];
    float4* sx4 = (float4*)sx;
    const float4* p4 = (const float4*)preds;
    for (int i = threadIdx.x; i < NN / 4; i += 256) sx4[i] = p4[i];
    __syncthreads();

    int warp = threadIdx.x >> 5;
    int lane = threadIdx.x & 31;
    int rb   = (blockIdx.x * 8 + warp) * 4;   // 4 rows per warp
    float x0 = sx[rb + 0];
    float x1 = sx[rb + 1];
    float x2 = sx[rb + 2];
    float x3 = sx[rb + 3];
    int c0 = 0, c1 = 0, c2 = 0, c3 = 0;
    #pragma unroll 4
    for (int t = 0; t < NN / 128; t++) {
        int j = t * 128 + lane * 4;
        float4 v = sx4[j >> 2];
        c0 += (v.x < x0) || (v.x == x0 && (j + 0) < rb);
        c0 += (v.y < x0) || (v.y == x0 && (j + 1) < rb);
        c0 += (v.z < x0) || (v.z == x0 && (j + 2) < rb);
        c0 += (v.w < x0) || (v.w == x0 && (j + 3) < rb);
        c1 += (v.x < x1) || (v.x == x1 && (j + 0) < rb + 1);
        c1 += (v.y < x1) || (v.y == x1 && (j + 1) < rb + 1);
        c1 += (v.z < x1) || (v.z == x1 && (j + 2) < rb + 1);
        c1 += (v.w < x1) || (v.w == x1 && (j + 3) < rb + 1);
        c2 += (v.x < x2) || (v.x == x2 && (j + 0) < rb + 2);
        c2 += (v.y < x2) || (v.y == x2 && (j + 1) < rb + 2);
        c2 += (v.z < x2) || (v.z == x2 && (j + 2) < rb + 2);
        c2 += (v.w < x2) || (v.w == x2 && (j + 3) < rb + 2);
        c3 += (v.x < x3) || (v.x == x3 && (j + 0) < rb + 3);
        c3 += (v.y < x3) || (v.y == x3 && (j + 1) < rb + 3);
        c3 += (v.z < x3) || (v.z == x3 && (j + 2) < rb + 3);
        c3 += (v.w < x3) || (v.w == x3 && (j + 3) < rb + 3);
    }
    #pragma unroll
    for (int off = 16; off; off >>= 1) {
        c0 += __shfl_xor_sync(FULL, c0, off);
        c1 += __shfl_xor_sync(FULL, c1, off);
        c2 += __shfl_xor_sync(FULL, c2, off);
        c3 += __shfl_xor_sync(FULL, c3, off);
    }
    if (lane == 0) {
        g_xs[c0] = x0; g_ts[c0] = target[rb + 0];
        g_xs[c1] = x1; g_ts[c1] = target[rb + 1];
        g_xs[c2] = x2; g_ts[c2] = target[rb + 2];
        g_xs[c3] = x3; g_ts[c3] = target[rb + 3];
    }
    if (blockIdx.x == 0 && threadIdx.x < 4) {
        g_xs[NN + threadIdx.x] = 1e30f;
        g_ts[NN + threadIdx.x] = 0.0f;
    }
    pdl_trigger();
}

// ---------------------------------------------------------------------------
// Kernel B: y_sorted[i] = softmax_j(-(xs_i - x_j)^2/tau) . t_j
// ---------------------------------------------------------------------------
__global__ void __launch_bounds__(1024)
ysoft_kernel() {
    const unsigned FULL = 0xffffffffu;
    __shared__ float sx[NN + 4];
    __shared__ float st_[NN + 4];
    pdl_wait();
    {
        float4* a = (float4*)sx;
        float4* b = (float4*)st_;
        const float4* ga = (const float4*)g_xs;
        const float4* gb = (const float4*)g_ts;
        a[threadIdx.x] = ga[threadIdx.x];
        b[threadIdx.x] = gb[threadIdx.x];
        if (threadIdx.x == 0) {
            a[NN / 4] = ga[NN / 4];
            b[NN / 4] = gb[NN / 4];
        }
    }
    __syncthreads();

    const int lane = threadIdx.x & 31;
    const int warp = threadIdx.x >> 5;
    const int row = blockIdx.x * 32 + warp;
    const float xv = sx[row];

    int lim = 0;
    if (lane < 2) {
        float tgt = (lane == 0) ? (xv - RWIN) : (xv + RWIN);
        int l = 0, r = NN;
        while (l < r) {
            int m = (l + r) >> 1;
            bool go = (lane == 0) ? (sx[m] < tgt) : (sx[m] <= tgt);
            if (go) l = m + 1; else r = m;
        }
        lim = l;
    }
    int lo = __shfl_sync(FULL, lim, 0);
    int hi = __shfl_sync(FULL, lim, 1);

    float se = 0.f, su = 0.f;
    int j0 = (lo & ~3) + lane * 4;
    for (int j = j0; j < hi; j += 128) {
        float4 x4 = *reinterpret_cast<const float4*>(sx + j);
        float4 t4 = *reinterpret_cast<const float4*>(st_ + j);
        float d0 = xv - x4.x, d1 = xv - x4.y, d2 = xv - x4.z, d3 = xv - x4.w;
        float a0 = (d0 * d0) * (-CEXP);
        float a1 = (d1 * d1) * (-CEXP);
        float a2 = (d2 * d2) * (-CEXP);
        float a3 = (d3 * d3) * (-CEXP);
        float e0, e1, e2, e3;
        asm("ex2.approx.f32 %0, %1;" : "=f"(e0) : "f"(a0));
        asm("ex2.approx.f32 %0, %1;" : "=f"(e1) : "f"(a1));
        asm("ex2.approx.f32 %0, %1;" : "=f"(e2) : "f"(a2));
        asm("ex2.approx.f32 %0, %1;" : "=f"(e3) : "f"(a3));
        se += e0 + e1 + e2 + e3;
        su = fmaf(e0, t4.x, su);
        su = fmaf(e1, t4.y, su);
        su = fmaf(e2, t4.z, su);
        su = fmaf(e3, t4.w, su);
    }
    for (int off = 16; off; off >>= 1) {
        se += __shfl_down_sync(FULL, se, off);
        su += __shfl_down_sync(FULL, su, off);
    }
    if (lane == 0) g_y[row] = su / se;
    pdl_trigger();
}

// ---------------------------------------------------------------------------
// Kernel D: rank-by-count DESCENDING argsort of y; 4 rows/warp, single wave.
// ---------------------------------------------------------------------------
__global__ void __launch_bounds__(256)
rank_scatter_y() {
    const unsigned FULL = 0xffffffffu;
    __shared__ float sy[NN];
    pdl_wait();
    float4* sy4 = (float4*)sy;
    const float4* y4 = (const float4*)g_y;
    for (int i = threadIdx.x; i < NN / 4; i += 256) sy4[i] = y4[i];
    __syncthreads();

    int warp = threadIdx.x >> 5;
    int lane = threadIdx.x & 31;
    int rb   = (blockIdx.x * 8 + warp) * 4;
    float y0 = sy[rb + 0];
    float y1 = sy[rb + 1];
    float y2 = sy[rb + 2];
    float y3 = sy[rb + 3];
    int c0 = 0, c1 = 0, c2 = 0, c3 = 0;
    #pragma unroll 4
    for (int t = 0; t < NN / 128; t++) {
        int j = t * 128 + lane * 4;
        float4 v = sy4[j >> 2];
        c0 += (v.x > y0) || (v.x == y0 && (j + 0) < rb);
        c0 += (v.y > y0) || (v.y == y0 && (j + 1) < rb);
        c0 += (v.z > y0) || (v.z == y0 && (j + 2) < rb);
        c0 += (v.w > y0) || (v.w == y0 && (j + 3) < rb);
        c1 += (v.x > y1) || (v.x == y1 && (j + 0) < rb + 1);
        c1 += (v.y > y1) || (v.y == y1 && (j + 1) < rb + 1);
        c1 += (v.z > y1) || (v.z == y1 && (j + 2) < rb + 1);
        c1 += (v.w > y1) || (v.w == y1 && (j + 3) < rb + 1);
        c2 += (v.x > y2) || (v.x == y2 && (j + 0) < rb + 2);
        c2 += (v.y > y2) || (v.y == y2 && (j + 1) < rb + 2);
        c2 += (v.z > y2) || (v.z == y2 && (j + 2) < rb + 2);
        c2 += (v.w > y2) || (v.w == y2 && (j + 3) < rb + 2);
        c3 += (v.x > y3) || (v.x == y3 && (j + 0) < rb + 3);
        c3 += (v.y > y3) || (v.y == y3 && (j + 1) < rb + 3);
        c3 += (v.z > y3) || (v.z == y3 && (j + 2) < rb + 3);
        c3 += (v.w > y3) || (v.w == y3 && (j + 3) < rb + 3);
    }
    #pragma unroll
    for (int off = 16; off; off >>= 1) {
        c0 += __shfl_xor_sync(FULL, c0, off);
        c1 += __shfl_xor_sync(FULL, c1, off);
        c2 += __shfl_xor_sync(FULL, c2, off);
        c3 += __shfl_xor_sync(FULL, c3, off);
    }
    if (lane == 0) {
        g_ss[c0] = y0 * 100.0f; g_sidx[c0] = rb + 0;
        g_ss[c1] = y1 * 100.0f; g_sidx[c1] = rb + 1;
        g_ss[c2] = y2 * 100.0f; g_sidx[c2] = rb + 2;
        g_ss[c3] = y3 * 100.0f; g_sidx[c3] = rb + 3;
    }
    pdl_trigger();
}

// ---------------------------------------------------------------------------
// Kernel C: soft_rank via PAV + loss. Single block, 1024 thr. (R10 version)
// ---------------------------------------------------------------------------
__global__ void __launch_bounds__(1024)
rank_kernel(float* out, int out_size) {
    extern __shared__ char smem_raw[];
    float4* pb     = (float4*)smem_raw;            // NN  (pre-blocks / stack)
    float*  r      = (float*)(pb + NN);            // NN  (zc prefix, then ranks)
    float*  fmean  = r + NN;                       // NN
    int*    bstart = (int*)(fmean + NN);           // NN+1
    int*    fstart = bstart + NN + 1;              // NN+1
    float*  sprev  = (float*)(fstart + NN + 1);    // 1024

    __shared__ int   warpTotI[32];
    __shared__ float warpTotF[32];
    __shared__ int   warpOffI[32];
    __shared__ float warpOffF[32];
    __shared__ int   s_m, s_nb;
    __shared__ float s_red[32];

    const unsigned FULL = 0xffffffffu;
    int tid  = threadIdx.x;
    int lane = tid & 31;
    int warp = tid >> 5;
    const int base = tid * 4;

    pdl_wait();
    float4 sv = ((const float4*)g_ss)[tid];
    int4   si = ((const int4*)g_sidx)[tid];
    sprev[tid] = sv.w;
    __syncthreads();

    float prev = (tid == 0) ? sv.x : sprev[tid - 1];
    int b0 = (base > 0) ? (prev - sv.x > 1.0f) : 0;
    int b1 = (sv.x - sv.y > 1.0f);
    int b2 = (sv.y - sv.z > 1.0f);
    int b3 = (sv.z - sv.w > 1.0f);
    int cb = b0 + b1 + b2 + b3;
    float zt = (sv.x + sv.y + sv.z + sv.w) - (float)(4 * NN - 4 * base - 6);

    int ic = cb; float fc = zt;
    for (int off = 1; off < 32; off <<= 1) {
        int   ui = __shfl_up_sync(FULL, ic, off);
        float uf = __shfl_up_sync(FULL, fc, off);
        if (lane >= off) { ic += ui; fc += uf; }
    }
    if (lane == 31) { warpTotI[warp] = ic; warpTotF[warp] = fc; }
    __syncthreads();
    if (warp == 0) {
        int   ti = warpTotI[lane];
        float tf = warpTotF[lane];
        int   vi = ti; float vf = tf;
        for (int off = 1; off < 32; off <<= 1) {
            int   ui = __shfl_up_sync(FULL, vi, off);
            float uf = __shfl_up_sync(FULL, vf, off);
            if (lane >= off) { vi += ui; vf += uf; }
        }
        warpOffI[lane] = vi - ti;
        warpOffF[lane] = vf - tf;
    }
    __syncthreads();
    int   exI = warpOffI[warp] + (ic - cb);
    float exF = warpOffF[warp] + (fc - zt);

    {
        int cc = exI;
        float zc = exF;
        cc += b0; if (b0) bstart[cc] = base + 0;
        zc += sv.x - (float)(NN - base - 0); r[base + 0] = zc;
        cc += b1; if (b1) bstart[cc] = base + 1;
        zc += sv.y - (float)(NN - base - 1); r[base + 1] = zc;
        cc += b2; if (b2) bstart[cc] = base + 2;
        zc += sv.z - (float)(NN - base - 2); r[base + 2] = zc;
        cc += b3; if (b3) bstart[cc] = base + 3;
        zc += sv.w - (float)(NN - base - 3); r[base + 3] = zc;
        if (tid == 0) bstart[0] = 0;
        if (tid == 1023) { s_m = cc + 1; bstart[cc + 1] = NN; }
    }
    __syncthreads();

    int m = s_m;
    for (int b = tid; b < m; b += 1024) {
        int st_ = bstart[b], en = bstart[b + 1];
        float lo_ = (st_ > 0) ? r[st_ - 1] : 0.f;
        pb[b] = make_float4(r[en - 1] - lo_, (float)(en - st_), (float)st_, 0.f);
    }
    __syncthreads();

    if (tid == 0) {
        int sp = 0;
        float4 c0 = pb[0];
        float tsum = c0.x, tcnt = c0.y, tstf = c0.z;
        float4 nxt = (m > 1) ? pb[1] : make_float4(0, 0, 0, 0);
        for (int b = 1; b < m; b++) {
            float4 c = nxt;
            if (b + 1 < m) nxt = pb[b + 1];
            float nsum = c.x, ncnt = c.y, nstf = c.z;
            bool havetop = true;
            while (havetop && tsum * ncnt <= nsum * tcnt) {
                nsum += tsum; ncnt += tcnt; nstf = tstf;
                if (sp > 0) {
                    sp--;
                    float4 tpv = pb[sp];
                    tsum = tpv.x; tcnt = tpv.y; tstf = tpv.z;
                } else {
                    havetop = false;
                }
            }
            if (havetop) {
                pb[sp] = make_float4(tsum, tcnt, tstf, 0.f);
                sp++;
            }
            tsum = nsum; tcnt = ncnt; tstf = nstf;
        }
        for (int q_ = 0; q_ < sp; q_++) {
            float4 v = pb[q_];
            fstart[q_] = (int)v.z;
            fmean[q_]  = v.x / v.y;
        }
        fstart[sp] = (int)tstf;
        fmean[sp]  = tsum / tcnt;
        fstart[sp + 1] = NN;
        s_nb = sp + 1;
    }
    __syncthreads();

    int nb = s_nb;
    #pragma unroll
    for (int e = 0; e < 4; e++) {
        int k = base + e;
        int l = 0, h = nb;
        while (l + 1 < h) {
            int mid = (l + h) >> 1;
            if (fstart[mid] <= k) l = mid; else h = mid;
        }
        float sval = (e == 0) ? sv.x : (e == 1) ? sv.y : (e == 2) ? sv.z : sv.w;
        int dst = (e == 0) ? si.x : (e == 1) ? si.y : (e == 2) ? si.z : si.w;
        r[dst] = sval - fmean[l];
    }
    __syncthreads();

    float acc = 0.f;
    for (int i = tid; i < NN - 1; i += 1024) acc += fabsf(r[i + 1] - r[i]);
    for (int off = 16; off; off >>= 1) acc += __shfl_down_sync(FULL, acc, off);
    if (lane == 0) s_red[warp] = acc;
    __syncthreads();
    if (warp == 0) {
        float a2 = s_red[lane];
        for (int off = 16; off; off >>= 1) a2 += __shfl_down_sync(FULL, a2, off);
        if (lane == 0) {
            float xi = 1.0f - 3.0f * a2 / ((float)NN * (float)NN - 1.0f);
            out[0] = -xi;
            if (out_size > 1) out[1] = xi;
        }
    }
}

// ---------------------------------------------------------------------------
extern "C" void kernel_launch(void* const* d_in, const int* in_sizes, int n_in,
                              void* d_out, int out_size) {
    const float* preds  = (const float*)d_in[0];
    const float* target = (const float*)d_in[1];
    float* out = (float*)d_out;

    size_t smemR = (size_t)NN * 32 + 8 + 4096;
    static int configured = 0;
    if (!configured) {
        cudaFuncSetAttribute(rank_kernel,
                             cudaFuncAttributeMaxDynamicSharedMemorySize,
                             (int)smemR);
        configured = 1;
    }

    rank_scatter_pairs<<<128, 256>>>(preds, target);

    cudaLaunchAttribute attr[1];
    attr[0].id = cudaLaunchAttributeProgrammaticStreamSerialization;
    attr[0].val.programmaticStreamSerializationAllowed = 1;

    {
        cudaLaunchConfig_t cfg = {};
        cfg.gridDim = dim3(NN / 32, 1, 1);
        cfg.blockDim = dim3(1024, 1, 1);
        cfg.dynamicSmemBytes = 0;
        cfg.attrs = attr;
        cfg.numAttrs = 1;
        cudaLaunchKernelEx(&cfg, ysoft_kernel);
    }
    {
        cudaLaunchConfig_t cfg = {};
        cfg.gridDim = dim3(128, 1, 1);
        cfg.blockDim = dim3(256, 1, 1);
        cfg.dynamicSmemBytes = 0;
        cfg.attrs = attr;
        cfg.numAttrs = 1;
        cudaLaunchKernelEx(&cfg, rank_scatter_y);
    }
    {
        cudaLaunchConfig_t cfg = {};
        cfg.gridDim = dim3(1, 1, 1);
        cfg.blockDim = dim3(1024, 1, 1);
        cfg.dynamicSmemBytes = smemR;
        cfg.attrs = attr;
        cfg.numAttrs = 1;
        cudaLaunchKernelEx(&cfg, rank_kernel, out, out_size);
    }
}

// round 15
// speedup vs baseline: 1.3014x; 1.1933x over previous
#include <cuda_runtime.h>
#include <math.h>

#define NN 4096
#define CEXP 144.269504089f   /* (1/TAU) * log2(e) */
#define RWIN 0.3725f          /* sqrt(20 / CEXP): exp2 term < 2^-20 beyond */

static __device__ float g_xs[NN + 4];   // preds sorted ascending (+padding)
static __device__ float g_ts[NN + 4];   // target permuted alongside (+padding)
static __device__ float g_y[NN];        // y_sorted
static __device__ float g_ss[NN];       // s = 100*y sorted DESCENDING
static __device__ int   g_sidx[NN];     // original indices of that sort

// ---- PDL primitives --------------------------------------------------------
__device__ __forceinline__ void pdl_wait() {
    asm volatile("griddepcontrol.wait;" ::: "memory");
}
__device__ __forceinline__ void pdl_trigger() {
    asm volatile("griddepcontrol.launch_dependents;" ::: "memory");
}

// ---------------------------------------------------------------------------
// Kernel A: rank-by-count sort of (preds, target) by preds ascending.
// 128 blocks x 256 thr (single wave), 4 rows/warp. Split-range compare:
// tiles before the rows' tile use (v <= x), after use (v < x); only the one
// boundary tile pays the full lexicographic tiebreak.
// ---------------------------------------------------------------------------
__global__ void __launch_bounds__(256)
rank_scatter_pairs(const float* __restrict__ preds,
                   const float* __restrict__ target) {
    const unsigned FULL = 0xffffffffu;
    __shared__ float sx[NN];
    float4* sx4 = (float4*)sx;
    const float4* p4 = (const float4*)preds;
    for (int i = threadIdx.x; i < NN / 4; i += 256) sx4[i] = p4[i];
    __syncthreads();

    int warp = threadIdx.x >> 5;
    int lane = threadIdx.x & 31;
    int rb   = (blockIdx.x * 8 + warp) * 4;   // rows rb..rb+3, all in tile Tr
    int Tr   = rb >> 7;
    float x0 = sx[rb + 0];
    float x1 = sx[rb + 1];
    float x2 = sx[rb + 2];
    float x3 = sx[rb + 3];
    int c0 = 0, c1 = 0, c2 = 0, c3 = 0;

    #pragma unroll 4
    for (int t = 0; t < Tr; t++) {            // j < rb for all rows: use <=
        float4 v = sx4[(t * 128 + lane * 4) >> 2];
        c0 += (v.x <= x0) + (v.y <= x0) + (v.z <= x0) + (v.w <= x0);
        c1 += (v.x <= x1) + (v.y <= x1) + (v.z <= x1) + (v.w <= x1);
        c2 += (v.x <= x2) + (v.y <= x2) + (v.z <= x2) + (v.w <= x2);
        c3 += (v.x <= x3) + (v.y <= x3) + (v.z <= x3) + (v.w <= x3);
    }
    {                                          // boundary tile: full tiebreak
        int j = Tr * 128 + lane * 4;
        float4 v = sx4[j >> 2];
        c0 += (v.x < x0) || (v.x == x0 && (j + 0) < rb);
        c0 += (v.y < x0) || (v.y == x0 && (j + 1) < rb);
        c0 += (v.z < x0) || (v.z == x0 && (j + 2) < rb);
        c0 += (v.w < x0) || (v.w == x0 && (j + 3) < rb);
        c1 += (v.x < x1) || (v.x == x1 && (j + 0) < rb + 1);
        c1 += (v.y < x1) || (v.y == x1 && (j + 1) < rb + 1);
        c1 += (v.z < x1) || (v.z == x1 && (j + 2) < rb + 1);
        c1 += (v.w < x1) || (v.w == x1 && (j + 3) < rb + 1);
        c2 += (v.x < x2) || (v.x == x2 && (j + 0) < rb + 2);
        c2 += (v.y < x2) || (v.y == x2 && (j + 1) < rb + 2);
        c2 += (v.z < x2) || (v.z == x2 && (j + 2) < rb + 2);
        c2 += (v.w < x2) || (v.w == x2 && (j + 3) < rb + 2);
        c3 += (v.x < x3) || (v.x == x3 && (j + 0) < rb + 3);
        c3 += (v.y < x3) || (v.y == x3 && (j + 1) < rb + 3);
        c3 += (v.z < x3) || (v.z == x3 && (j + 2) < rb + 3);
        c3 += (v.w < x3) || (v.w == x3 && (j + 3) < rb + 3);
    }
    #pragma unroll 4
    for (int t = Tr + 1; t < NN / 128; t++) {  // j > rb+3 for all rows: use <
        float4 v = sx4[(t * 128 + lane * 4) >> 2];
        c0 += (v.x < x0) + (v.y < x0) + (v.z < x0) + (v.w < x0);
        c1 += (v.x < x1) + (v.y < x1) + (v.z < x1) + (v.w < x1);
        c2 += (v.x < x2) + (v.y < x2) + (v.z < x2) + (v.w < x2);
        c3 += (v.x < x3) + (v.y < x3) + (v.z < x3) + (v.w < x3);
    }
    #pragma unroll
    for (int off = 16; off; off >>= 1) {
        c0 += __shfl_xor_sync(FULL, c0, off);
        c1 += __shfl_xor_sync(FULL, c1, off);
        c2 += __shfl_xor_sync(FULL, c2, off);
        c3 += __shfl_xor_sync(FULL, c3, off);
    }
    if (lane == 0) {
        g_xs[c0] = x0; g_ts[c0] = target[rb + 0];
        g_xs[c1] = x1; g_ts[c1] = target[rb + 1];
        g_xs[c2] = x2; g_ts[c2] = target[rb + 2];
        g_xs[c3] = x3; g_ts[c3] = target[rb + 3];
    }
    if (blockIdx.x == 0 && threadIdx.x < 4) {
        g_xs[NN + threadIdx.x] = 1e30f;
        g_ts[NN + threadIdx.x] = 0.0f;
    }
    pdl_trigger();
}

// ---------------------------------------------------------------------------
// Kernel B: y_sorted[i] = softmax_j(-(xs_i - x_j)^2/tau) . t_j
// ---------------------------------------------------------------------------
__global__ void __launch_bounds__(1024)
ysoft_kernel() {
    const unsigned FULL = 0xffffffffu;
    __shared__ float sx[NN + 4];
    __shared__ float st_[NN + 4];
    pdl_wait();
    {
        float4* a = (float4*)sx;
        float4* b = (float4*)st_;
        const float4* ga = (const float4*)g_xs;
        const float4* gb = (const float4*)g_ts;
        a[threadIdx.x] = ga[threadIdx.x];
        b[threadIdx.x] = gb[threadIdx.x];
        if (threadIdx.x == 0) {
            a[NN / 4] = ga[NN / 4];
            b[NN / 4] = gb[NN / 4];
        }
    }
    __syncthreads();

    const int lane = threadIdx.x & 31;
    const int warp = threadIdx.x >> 5;
    const int row = blockIdx.x * 32 + warp;
    const float xv = sx[row];

    int lim = 0;
    if (lane < 2) {
        float tgt = (lane == 0) ? (xv - RWIN) : (xv + RWIN);
        int l = 0, r = NN;
        while (l < r) {
            int m = (l + r) >> 1;
            bool go = (lane == 0) ? (sx[m] < tgt) : (sx[m] <= tgt);
            if (go) l = m + 1; else r = m;
        }
        lim = l;
    }
    int lo = __shfl_sync(FULL, lim, 0);
    int hi = __shfl_sync(FULL, lim, 1);

    float se = 0.f, su = 0.f;
    int j0 = (lo & ~3) + lane * 4;
    for (int j = j0; j < hi; j += 128) {
        float4 x4 = *reinterpret_cast<const float4*>(sx + j);
        float4 t4 = *reinterpret_cast<const float4*>(st_ + j);
        float d0 = xv - x4.x, d1 = xv - x4.y, d2 = xv - x4.z, d3 = xv - x4.w;
        float a0 = (d0 * d0) * (-CEXP);
        float a1 = (d1 * d1) * (-CEXP);
        float a2 = (d2 * d2) * (-CEXP);
        float a3 = (d3 * d3) * (-CEXP);
        float e0, e1, e2, e3;
        asm("ex2.approx.f32 %0, %1;" : "=f"(e0) : "f"(a0));
        asm("ex2.approx.f32 %0, %1;" : "=f"(e1) : "f"(a1));
        asm("ex2.approx.f32 %0, %1;" : "=f"(e2) : "f"(a2));
        asm("ex2.approx.f32 %0, %1;" : "=f"(e3) : "f"(a3));
        se += e0 + e1 + e2 + e3;
        su = fmaf(e0, t4.x, su);
        su = fmaf(e1, t4.y, su);
        su = fmaf(e2, t4.z, su);
        su = fmaf(e3, t4.w, su);
    }
    for (int off = 16; off; off >>= 1) {
        se += __shfl_down_sync(FULL, se, off);
        su += __shfl_down_sync(FULL, su, off);
    }
    if (lane == 0) g_y[row] = su / se;
    pdl_trigger();
}

// ---------------------------------------------------------------------------
// Kernel D: descending argsort of y; 4 rows/warp, split-range compare.
// ---------------------------------------------------------------------------
__global__ void __launch_bounds__(256)
rank_scatter_y() {
    const unsigned FULL = 0xffffffffu;
    __shared__ float sy[NN];
    pdl_wait();
    float4* sy4 = (float4*)sy;
    const float4* y4 = (const float4*)g_y;
    for (int i = threadIdx.x; i < NN / 4; i += 256) sy4[i] = y4[i];
    __syncthreads();

    int warp = threadIdx.x >> 5;
    int lane = threadIdx.x & 31;
    int rb   = (blockIdx.x * 8 + warp) * 4;
    int Tr   = rb >> 7;
    float y0 = sy[rb + 0];
    float y1 = sy[rb + 1];
    float y2 = sy[rb + 2];
    float y3 = sy[rb + 3];
    int c0 = 0, c1 = 0, c2 = 0, c3 = 0;

    #pragma unroll 4
    for (int t = 0; t < Tr; t++) {            // j < rb: use >=
        float4 v = sy4[(t * 128 + lane * 4) >> 2];
        c0 += (v.x >= y0) + (v.y >= y0) + (v.z >= y0) + (v.w >= y0);
        c1 += (v.x >= y1) + (v.y >= y1) + (v.z >= y1) + (v.w >= y1);
        c2 += (v.x >= y2) + (v.y >= y2) + (v.z >= y2) + (v.w >= y2);
        c3 += (v.x >= y3) + (v.y >= y3) + (v.z >= y3) + (v.w >= y3);
    }
    {                                          // boundary tile: full tiebreak
        int j = Tr * 128 + lane * 4;
        float4 v = sy4[j >> 2];
        c0 += (v.x > y0) || (v.x == y0 && (j + 0) < rb);
        c0 += (v.y > y0) || (v.y == y0 && (j + 1) < rb);
        c0 += (v.z > y0) || (v.z == y0 && (j + 2) < rb);
        c0 += (v.w > y0) || (v.w == y0 && (j + 3) < rb);
        c1 += (v.x > y1) || (v.x == y1 && (j + 0) < rb + 1);
        c1 += (v.y > y1) || (v.y == y1 && (j + 1) < rb + 1);
        c1 += (v.z > y1) || (v.z == y1 && (j + 2) < rb + 1);
        c1 += (v.w > y1) || (v.w == y1 && (j + 3) < rb + 1);
        c2 += (v.x > y2) || (v.x == y2 && (j + 0) < rb + 2);
        c2 += (v.y > y2) || (v.y == y2 && (j + 1) < rb + 2);
        c2 += (v.z > y2) || (v.z == y2 && (j + 2) < rb + 2);
        c2 += (v.w > y2) || (v.w == y2 && (j + 3) < rb + 2);
        c3 += (v.x > y3) || (v.x == y3 && (j + 0) < rb + 3);
        c3 += (v.y > y3) || (v.y == y3 && (j + 1) < rb + 3);
        c3 += (v.z > y3) || (v.z == y3 && (j + 2) < rb + 3);
        c3 += (v.w > y3) || (v.w == y3 && (j + 3) < rb + 3);
    }
    #pragma unroll 4
    for (int t = Tr + 1; t < NN / 128; t++) {  // j > rb+3: use >
        float4 v = sy4[(t * 128 + lane * 4) >> 2];
        c0 += (v.x > y0) + (v.y > y0) + (v.z > y0) + (v.w > y0);
        c1 += (v.x > y1) + (v.y > y1) + (v.z > y1) + (v.w > y1);
        c2 += (v.x > y2) + (v.y > y2) + (v.z > y2) + (v.w > y2);
        c3 += (v.x > y3) + (v.y > y3) + (v.z > y3) + (v.w > y3);
    }
    #pragma unroll
    for (int off = 16; off; off >>= 1) {
        c0 += __shfl_xor_sync(FULL, c0, off);
        c1 += __shfl_xor_sync(FULL, c1, off);
        c2 += __shfl_xor_sync(FULL, c2, off);
        c3 += __shfl_xor_sync(FULL, c3, off);
    }
    if (lane == 0) {
        g_ss[c0] = y0 * 100.0f; g_sidx[c0] = rb + 0;
        g_ss[c1] = y1 * 100.0f; g_sidx[c1] = rb + 1;
        g_ss[c2] = y2 * 100.0f; g_sidx[c2] = rb + 2;
        g_ss[c3] = y3 * 100.0f; g_sidx[c3] = rb + 3;
    }
    pdl_trigger();
}

// ---------------------------------------------------------------------------
// Kernel C: soft_rank via PAV + loss. Single block, 1024 thr. (R10 version)
// ---------------------------------------------------------------------------
__global__ void __launch_bounds__(1024)
rank_kernel(float* out, int out_size) {
    extern __shared__ char smem_raw[];
    float4* pb     = (float4*)smem_raw;            // NN  (pre-blocks / stack)
    float*  r      = (float*)(pb + NN);            // NN  (zc prefix, then ranks)
    float*  fmean  = r + NN;                       // NN
    int*    bstart = (int*)(fmean + NN);           // NN+1
    int*    fstart = bstart + NN + 1;              // NN+1
    float*  sprev  = (float*)(fstart + NN + 1);    // 1024

    __shared__ int   warpTotI[32];
    __shared__ float warpTotF[32];
    __shared__ int   warpOffI[32];
    __shared__ float warpOffF[32];
    __shared__ int   s_m, s_nb;
    __shared__ float s_red[32];

    const unsigned FULL = 0xffffffffu;
    int tid  = threadIdx.x;
    int lane = tid & 31;
    int warp = tid >> 5;
    const int base = tid * 4;

    pdl_wait();
    float4 sv = ((const float4*)g_ss)[tid];
    int4   si = ((const int4*)g_sidx)[tid];
    sprev[tid] = sv.w;
    __syncthreads();

    float prev = (tid == 0) ? sv.x : sprev[tid - 1];
    int b0 = (base > 0) ? (prev - sv.x > 1.0f) : 0;
    int b1 = (sv.x - sv.y > 1.0f);
    int b2 = (sv.y - sv.z > 1.0f);
    int b3 = (sv.z - sv.w > 1.0f);
    int cb = b0 + b1 + b2 + b3;
    float zt = (sv.x + sv.y + sv.z + sv.w) - (float)(4 * NN - 4 * base - 6);

    int ic = cb; float fc = zt;
    for (int off = 1; off < 32; off <<= 1) {
        int   ui = __shfl_up_sync(FULL, ic, off);
        float uf = __shfl_up_sync(FULL, fc, off);
        if (lane >= off) { ic += ui; fc += uf; }
    }
    if (lane == 31) { warpTotI[warp] = ic; warpTotF[warp] = fc; }
    __syncthreads();
    if (warp == 0) {
        int   ti = warpTotI[lane];
        float tf = warpTotF[lane];
        int   vi = ti; float vf = tf;
        for (int off = 1; off < 32; off <<= 1) {
            int   ui = __shfl_up_sync(FULL, vi, off);
            float uf = __shfl_up_sync(FULL, vf, off);
            if (lane >= off) { vi += ui; vf += uf; }
        }
        warpOffI[lane] = vi - ti;
        warpOffF[lane] = vf - tf;
    }
    __syncthreads();
    int   exI = warpOffI[warp] + (ic - cb);
    float exF = warpOffF[warp] + (fc - zt);

    {
        int cc = exI;
        float zc = exF;
        cc += b0; if (b0) bstart[cc] = base + 0;
        zc += sv.x - (float)(NN - base - 0); r[base + 0] = zc;
        cc += b1; if (b1) bstart[cc] = base + 1;
        zc += sv.y - (float)(NN - base - 1); r[base + 1] = zc;
        cc += b2; if (b2) bstart[cc] = base + 2;
        zc += sv.z - (float)(NN - base - 2); r[base + 2] = zc;
        cc += b3; if (b3) bstart[cc] = base + 3;
        zc += sv.w - (float)(NN - base - 3); r[base + 3] = zc;
        if (tid == 0) bstart[0] = 0;
        if (tid == 1023) { s_m = cc + 1; bstart[cc + 1] = NN; }
    }
    __syncthreads();

    int m = s_m;
    for (int b = tid; b < m; b += 1024) {
        int st_ = bstart[b], en = bstart[b + 1];
        float lo_ = (st_ > 0) ? r[st_ - 1] : 0.f;
        pb[b] = make_float4(r[en - 1] - lo_, (float)(en - st_), (float)st_, 0.f);
    }
    __syncthreads();

    if (tid == 0) {
        int sp = 0;
        float4 c0 = pb[0];
        float tsum = c0.x, tcnt = c0.y, tstf = c0.z;
        float4 nxt = (m > 1) ? pb[1] : make_float4(0, 0, 0, 0);
        for (int b = 1; b < m; b++) {
            float4 c = nxt;
            if (b + 1 < m) nxt = pb[b + 1];
            float nsum = c.x, ncnt = c.y, nstf = c.z;
            bool havetop = true;
            while (havetop && tsum * ncnt <= nsum * tcnt) {
                nsum += tsum; ncnt += tcnt; nstf = tstf;
                if (sp > 0) {
                    sp--;
                    float4 tpv = pb[sp];
                    tsum = tpv.x; tcnt = tpv.y; tstf = tpv.z;
                } else {
                    havetop = false;
                }
            }
            if (havetop) {
                pb[sp] = make_float4(tsum, tcnt, tstf, 0.f);
                sp++;
            }
            tsum = nsum; tcnt = ncnt; tstf = nstf;
        }
        for (int q_ = 0; q_ < sp; q_++) {
            float4 v = pb[q_];
            fstart[q_] = (int)v.z;
            fmean[q_]  = v.x / v.y;
        }
        fstart[sp] = (int)tstf;
        fmean[sp]  = tsum / tcnt;
        fstart[sp + 1] = NN;
        s_nb = sp + 1;
    }
    __syncthreads();

    int nb = s_nb;
    #pragma unroll
    for (int e = 0; e < 4; e++) {
        int k = base + e;
        int l = 0, h = nb;
        while (l + 1 < h) {
            int mid = (l + h) >> 1;
            if (fstart[mid] <= k) l = mid; else h = mid;
        }
        float sval = (e == 0) ? sv.x : (e == 1) ? sv.y : (e == 2) ? sv.z : sv.w;
        int dst = (e == 0) ? si.x : (e == 1) ? si.y : (e == 2) ? si.z : si.w;
        r[dst] = sval - fmean[l];
    }
    __syncthreads();

    float acc = 0.f;
    for (int i = tid; i < NN - 1; i += 1024) acc += fabsf(r[i + 1] - r[i]);
    for (int off = 16; off; off >>= 1) acc += __shfl_down_sync(FULL, acc, off);
    if (lane == 0) s_red[warp] = acc;
    __syncthreads();
    if (warp == 0) {
        float a2 = s_red[lane];
        for (int off = 16; off; off >>= 1) a2 += __shfl_down_sync(FULL, a2, off);
        if (lane == 0) {
            float xi = 1.0f - 3.0f * a2 / ((float)NN * (float)NN - 1.0f);
            out[0] = -xi;
            if (out_size > 1) out[1] = xi;
        }
    }
}

// ---------------------------------------------------------------------------
extern "C" void kernel_launch(void* const* d_in, const int* in_sizes, int n_in,
                              void* d_out, int out_size) {
    const float* preds  = (const float*)d_in[0];
    const float* target = (const float*)d_in[1];
    float* out = (float*)d_out;

    size_t smemR = (size_t)NN * 32 + 8 + 4096;
    static int configured = 0;
    if (!configured) {
        cudaFuncSetAttribute(rank_kernel,
                             cudaFuncAttributeMaxDynamicSharedMemorySize,
                             (int)smemR);
        configured = 1;
    }

    rank_scatter_pairs<<<128, 256>>>(preds, target);

    cudaLaunchAttribute attr[1];
    attr[0].id = cudaLaunchAttributeProgrammaticStreamSerialization;
    attr[0].val.programmaticStreamSerializationAllowed = 1;

    {
        cudaLaunchConfig_t cfg = {};
        cfg.gridDim = dim3(NN / 32, 1, 1);
        cfg.blockDim = dim3(1024, 1, 1);
        cfg.dynamicSmemBytes = 0;
        cfg.attrs = attr;
        cfg.numAttrs = 1;
        cudaLaunchKernelEx(&cfg, ysoft_kernel);
    }
    {
        cudaLaunchConfig_t cfg = {};
        cfg.gridDim = dim3(128, 1, 1);
        cfg.blockDim = dim3(256, 1, 1);
        cfg.dynamicSmemBytes = 0;
        cfg.attrs = attr;
        cfg.numAttrs = 1;
        cudaLaunchKernelEx(&cfg, rank_scatter_y);
    }
    {
        cudaLaunchConfig_t cfg = {};
        cfg.gridDim = dim3(1, 1, 1);
        cfg.blockDim = dim3(1024, 1, 1);
        cfg.dynamicSmemBytes = smemR;
        cfg.attrs = attr;
        cfg.numAttrs = 1;
        cudaLaunchKernelEx(&cfg, rank_kernel, out, out_size);
    }
}